// round 2
// baseline (speedup 1.0000x reference)
#include <cuda_runtime.h>
#include <math.h>

#define FULL 0xffffffffu

// Problem constants
#define Bz 2
#define Sdim 2048
#define Edim 256
#define Hn 8
#define HD 32
#define WIN 129
#define OFF 64
#define MTOK (Bz*Sdim)          // 4096 token rows

// Scratch (no cudaMalloc allowed)
__device__ float g_xpe[MTOK*Edim];
__device__ float g_q[MTOK*Edim];
__device__ float g_k[MTOK*Edim];
__device__ float g_v[MTOK*Edim];
__device__ float g_ctx[MTOK*Edim];

// ---------------------------------------------------------------------------
// x + sinusoidal positional encoding
// ---------------------------------------------------------------------------
__global__ void add_pe_kernel(const float* __restrict__ x, float* __restrict__ y) {
    int i = blockIdx.x * 256 + threadIdx.x;      // exactly MTOK*Edim threads
    int e = i & (Edim - 1);
    int s = (i >> 8) & (Sdim - 1);
    // div = exp(2*(e/2) * (-ln(10000)/256))
    float dv = expf((float)(e >> 1) * (-2.0f * 9.210340371976184f / 256.0f));
    float ang = (float)s * dv;
    float pe = (e & 1) ? cosf(ang) : sinf(ang);
    y[i] = x[i] + pe;
}

// ---------------------------------------------------------------------------
// Y[M,256] = X[M,256] @ W[256,256] + bias   (fp32, 64x64x16 tiles, 256 thr)
// ---------------------------------------------------------------------------
#define BM 64
#define BN 64
#define BK 16
__global__ __launch_bounds__(256) void gemm_bias_kernel(
    const float* __restrict__ X, const float* __restrict__ W,
    const float* __restrict__ bias, float* __restrict__ Y)
{
    __shared__ float As[BK][BM];
    __shared__ float Bs[BK][BN];

    int t = threadIdx.x;
    int bm = blockIdx.x * BM;
    int bn = blockIdx.y * BN;

    int tm = (t & 15) * 4;       // m0 within tile
    int tn = (t >> 4) * 4;       // n0 within tile

    float acc[4][4];
#pragma unroll
    for (int i = 0; i < 4; ++i)
#pragma unroll
        for (int j = 0; j < 4; ++j) acc[i][j] = 0.f;

    for (int k0 = 0; k0 < Edim; k0 += BK) {
        {   // A tile: 64 rows x 16 k, stored As[k][m]
            int m  = t >> 2;
            int kq = (t & 3) * 4;
            float4 a = *(const float4*)&X[(bm + m) * Edim + k0 + kq];
            As[kq + 0][m] = a.x;
            As[kq + 1][m] = a.y;
            As[kq + 2][m] = a.z;
            As[kq + 3][m] = a.w;
        }
        {   // B tile: 16 k x 64 n
            int kk = t >> 4;
            int n  = (t & 15) * 4;
            *(float4*)&Bs[kk][n] = *(const float4*)&W[(k0 + kk) * Edim + bn + n];
        }
        __syncthreads();
#pragma unroll
        for (int kk = 0; kk < BK; ++kk) {
            float a[4], bb[4];
            *(float4*)a  = *(const float4*)&As[kk][tm];
            *(float4*)bb = *(const float4*)&Bs[kk][tn];
#pragma unroll
            for (int i = 0; i < 4; ++i)
#pragma unroll
                for (int j = 0; j < 4; ++j)
                    acc[i][j] = fmaf(a[i], bb[j], acc[i][j]);
        }
        __syncthreads();
    }

    float4 bv = *(const float4*)&bias[bn + tn];
#pragma unroll
    for (int i = 0; i < 4; ++i) {
        float4 o;
        o.x = acc[i][0] + bv.x;
        o.y = acc[i][1] + bv.y;
        o.z = acc[i][2] + bv.z;
        o.w = acc[i][3] + bv.w;
        *(float4*)&Y[(bm + tm + i) * Edim + bn + tn] = o;
    }
}

// ---------------------------------------------------------------------------
// Windowed attention. Block: 256 thr (8 warps), handles TS=32 positions for
// one (b, h). K/V tile staged in smem (padded rows, conflict-free).
// ---------------------------------------------------------------------------
#define TS 32
#define ROWS (TS + 128)          // 160
#define RP 33                    // padded row stride

__global__ __launch_bounds__(256) void attn_kernel(
    const float* __restrict__ q, const float* __restrict__ k,
    const float* __restrict__ v, float* __restrict__ ctx,
    float* __restrict__ attn_out)
{
    __shared__ float ks[ROWS * RP];
    __shared__ float vs[ROWS * RP];
    __shared__ float p_sm[8][132];

    const int b    = blockIdx.z;
    const int h    = blockIdx.y;
    const int s0   = blockIdx.x * TS;
    const int t    = threadIdx.x;
    const int lane = t & 31;
    const int warp = t >> 5;

    const int base = (b * Sdim) * Edim + h * HD;   // fits in int (max ~1M)

    // Stage K/V tile: rows r -> global token clamp(s0 - 64 + r)
#pragma unroll
    for (int it = 0; it < ROWS / 8; ++it) {
        int r = warp + it * 8;
        int tok = s0 - OFF + r;
        tok = min(max(tok, 0), Sdim - 1);
        int g = base + tok * Edim + lane;
        ks[r * RP + lane] = k[g];
        vs[r * RP + lane] = v[g];
    }
    __syncthreads();

    const float scale = 0.17677669529663689f;  // 1/sqrt(32)

    for (int i = 0; i < TS / 8; ++i) {
        int sl = warp * (TS / 8) + i;          // local s in [0,32)
        int s  = s0 + sl;
        float qd = q[base + s * Edim + lane];  // lane = d

        // ---- scores: lane owns w = lane + 32j (j<4), lane0 also w=128 ----
        int r0 = (sl + lane +  0) * RP;
        int r1 = (sl + lane + 32) * RP;
        int r2 = (sl + lane + 64) * RP;
        int r3 = (sl + lane + 96) * RP;
        int r4 = min(sl + lane + 128, ROWS - 1) * RP;

        float sum0 = 0.f, sum1 = 0.f, sum2 = 0.f, sum3 = 0.f, sum4 = 0.f;
#pragma unroll
        for (int d = 0; d < HD; ++d) {
            float a = __shfl_sync(FULL, qd, d);
            sum0 = fmaf(a, ks[r0 + d], sum0);
            sum1 = fmaf(a, ks[r1 + d], sum1);
            sum2 = fmaf(a, ks[r2 + d], sum2);
            sum3 = fmaf(a, ks[r3 + d], sum3);
            sum4 = fmaf(a, ks[r4 + d], sum4);
        }

        float sc[5];
        {
            int w, idx;
            w = lane +  0; idx = s + w - OFF;
            sc[0] = (idx >= 0 && idx < Sdim) ? sum0 * scale : -1e9f;
            w = lane + 32; idx = s + w - OFF;
            sc[1] = (idx >= 0 && idx < Sdim) ? sum1 * scale : -1e9f;
            w = lane + 64; idx = s + w - OFF;
            sc[2] = (idx >= 0 && idx < Sdim) ? sum2 * scale : -1e9f;
            w = lane + 96; idx = s + w - OFF;
            sc[3] = (idx >= 0 && idx < Sdim) ? sum3 * scale : -1e9f;
            idx = s + 128 - OFF;
            sc[4] = (lane == 0) ? ((idx < Sdim) ? sum4 * scale : -1e9f)
                                : -INFINITY;
        }

        // ---- softmax over 129 values distributed across lanes ----
        float m = sc[0];
#pragma unroll
        for (int j = 1; j < 5; ++j) m = fmaxf(m, sc[j]);
#pragma unroll
        for (int o = 16; o; o >>= 1) m = fmaxf(m, __shfl_xor_sync(FULL, m, o));

        float ex[5], lsum = 0.f;
#pragma unroll
        for (int j = 0; j < 5; ++j) { ex[j] = expf(sc[j] - m); lsum += ex[j]; }
#pragma unroll
        for (int o = 16; o; o >>= 1) lsum += __shfl_xor_sync(FULL, lsum, o);
        float inv = 1.f / lsum;

        int arow = ((b * Hn + h) * Sdim + s) * WIN;
#pragma unroll
        for (int j = 0; j < 4; ++j) {
            int w = lane + 32 * j;
            float p = ex[j] * inv;
            p_sm[warp][w] = p;
            if (attn_out) attn_out[arow + w] = p;
        }
        if (lane == 0) {
            float p = ex[4] * inv;
            p_sm[warp][128] = p;
            if (attn_out) attn_out[arow + 128] = p;
        }
        __syncwarp();

        // ---- ctx: lane = d ----
        float cacc = 0.f;
        int vb = sl * RP + lane;
#pragma unroll 8
        for (int w = 0; w < WIN; ++w)
            cacc = fmaf(p_sm[warp][w], vs[vb + w * RP], cacc);

        ctx[base + s * Edim + lane] = cacc;
        __syncwarp();
    }
}

// ---------------------------------------------------------------------------
extern "C" void kernel_launch(void* const* d_in, const int* in_sizes, int n_in,
                              void* d_out, int out_size) {
    const float* x  = (const float*)d_in[0];
    const float* Wq = (const float*)d_in[1];
    const float* bq = (const float*)d_in[2];
    const float* Wk = (const float*)d_in[3];
    const float* bk = (const float*)d_in[4];
    const float* Wv = (const float*)d_in[5];
    const float* bv = (const float*)d_in[6];
    const float* Wo = (const float*)d_in[7];
    const float* bo = (const float*)d_in[8];
    float* out = (float*)d_out;

    float *xpe, *q, *k, *v, *ctx;
    cudaGetSymbolAddress((void**)&xpe, g_xpe);
    cudaGetSymbolAddress((void**)&q,   g_q);
    cudaGetSymbolAddress((void**)&k,   g_k);
    cudaGetSymbolAddress((void**)&v,   g_v);
    cudaGetSymbolAddress((void**)&ctx, g_ctx);

    const long OUT_ELEMS  = (long)Bz * Sdim * Edim;                 // 1,048,576
    const long ATTN_ELEMS = (long)Bz * Hn * Sdim * WIN;             // 4,227,072
    float* attn_out = nullptr;
    if ((long)out_size >= OUT_ELEMS + ATTN_ELEMS) attn_out = out + OUT_ELEMS;

    add_pe_kernel<<<MTOK * Edim / 256, 256>>>(x, xpe);

    dim3 gg(MTOK / BM, Edim / BN);
    gemm_bias_kernel<<<gg, 256>>>(xpe, Wq, bq, q);
    gemm_bias_kernel<<<gg, 256>>>(xpe, Wk, bk, k);
    gemm_bias_kernel<<<gg, 256>>>(xpe, Wv, bv, v);

    attn_kernel<<<dim3(Sdim / TS, Hn, Bz), 256>>>(q, k, v, ctx, attn_out);

    gemm_bias_kernel<<<gg, 256>>>(ctx, Wo, bo, out);
}

// round 5
// speedup vs baseline: 1.3333x; 1.3333x over previous
#include <cuda_runtime.h>
#include <math.h>
#include <stdint.h>

#define FULL 0xffffffffu

// Problem constants
#define Bz 2
#define Sdim 2048
#define Edim 256
#define Hn 8
#define HD 32
#define WIN 129
#define OFF 64
#define MTOK (Bz*Sdim)          // 4096 token rows

// Scratch (no cudaMalloc allowed)
__device__ float g_xpe[MTOK*Edim];
__device__ float g_q[MTOK*Edim];
__device__ float g_k[MTOK*Edim];
__device__ float g_v[MTOK*Edim];
__device__ float g_ctx[MTOK*Edim];

// ---------------------------------------------------------------------------
// x + sinusoidal positional encoding
// ---------------------------------------------------------------------------
__global__ void add_pe_kernel(const float* __restrict__ x, float* __restrict__ y) {
    int i = blockIdx.x * 256 + threadIdx.x;      // exactly MTOK*Edim threads
    int e = i & (Edim - 1);
    int s = (i >> 8) & (Sdim - 1);
    float dv = expf((float)(e >> 1) * (-2.0f * 9.210340371976184f / 256.0f));
    float ang = (float)s * dv;
    float pe = (e & 1) ? cosf(ang) : sinf(ang);
    y[i] = x[i] + pe;
}

// ---------------------------------------------------------------------------
// 3xTF32 tensor-core GEMM: Y[M,256] = X[M,256] @ W[256,256] + bias
// Each operand split hi/lo via cvt.rna.tf32; acc += lo*hi + hi*lo + hi*hi
// gives near-fp32 precision at 3x tf32-MMA cost.
// CTA tile 128x64, 8 warps (4x2), warp tile 32x32 (2x4 m16n8k8 frags).
// K chunk 16, double-buffered cp.async. QKV fused via grid.y.
// ---------------------------------------------------------------------------
#define GBM 128
#define GBN 64
#define GBK 16
#define APAD 20
#define BPAD 72

__device__ __forceinline__ void cp16(void* smem, const void* g) {
    uint32_t s = (uint32_t)__cvta_generic_to_shared(smem);
    asm volatile("cp.async.cg.shared.global [%0], [%1], 16;\n" :: "r"(s), "l"(g));
}
__device__ __forceinline__ void cp_commit() {
    asm volatile("cp.async.commit_group;\n");
}
__device__ __forceinline__ void split_tf32(float x, uint32_t& hi, uint32_t& lo) {
    asm("cvt.rna.tf32.f32 %0, %1;" : "=r"(hi) : "f"(x));
    float l = x - __uint_as_float(hi);
    asm("cvt.rna.tf32.f32 %0, %1;" : "=r"(lo) : "f"(l));
}
__device__ __forceinline__ void mma_tf32(float* acc, const uint32_t* a, const uint32_t* b) {
    asm volatile(
        "mma.sync.aligned.m16n8k8.row.col.f32.tf32.tf32.f32 "
        "{%0,%1,%2,%3}, {%4,%5,%6,%7}, {%8,%9}, {%0,%1,%2,%3};\n"
        : "+f"(acc[0]), "+f"(acc[1]), "+f"(acc[2]), "+f"(acc[3])
        : "r"(a[0]), "r"(a[1]), "r"(a[2]), "r"(a[3]), "r"(b[0]), "r"(b[1]));
}

__global__ __launch_bounds__(256) void gemm_tc_kernel(
    const float* __restrict__ X,
    const float* __restrict__ W0, const float* __restrict__ b0, float* __restrict__ Y0,
    const float* __restrict__ W1, const float* __restrict__ b1, float* __restrict__ Y1,
    const float* __restrict__ W2, const float* __restrict__ b2, float* __restrict__ Y2)
{
    __shared__ float As[2][GBM][APAD];
    __shared__ float Bs[2][GBK][BPAD];

    const int t    = threadIdx.x;
    const int lane = t & 31;
    const int warp = t >> 5;
    const int warp_m = warp & 3;
    const int warp_n = warp >> 2;

    const int bm = blockIdx.x * GBM;
    const int wsel = blockIdx.y >> 2;
    const int bn = (blockIdx.y & 3) * GBN;

    const float* W    = (wsel == 0) ? W0 : ((wsel == 1) ? W1 : W2);
    const float* bias = (wsel == 0) ? b0 : ((wsel == 1) ? b1 : b2);
    float*       Y    = (wsel == 0) ? Y0 : ((wsel == 1) ? Y1 : Y2);

    float acc[2][4][4];
#pragma unroll
    for (int mf = 0; mf < 2; ++mf)
#pragma unroll
        for (int nf = 0; nf < 4; ++nf)
#pragma unroll
            for (int r = 0; r < 4; ++r) acc[mf][nf][r] = 0.f;

    const int am  = t >> 2;
    const int akq = (t & 3) * 4;
    const int bkk = t >> 4;
    const int bnq = (t & 15) * 4;

#define LOAD_TILE(it, buf)                                                     \
    do {                                                                       \
        int k0_ = (it) * GBK;                                                  \
        cp16(&As[buf][am][akq],       &X[(bm + am) * Edim + k0_ + akq]);       \
        cp16(&As[buf][am + 64][akq],  &X[(bm + am + 64) * Edim + k0_ + akq]);  \
        cp16(&Bs[buf][bkk][bnq],      &W[(k0_ + bkk) * Edim + bn + bnq]);      \
        cp_commit();                                                           \
    } while (0)

    LOAD_TILE(0, 0);

    const int KITERS = Edim / GBK;   // 16
    for (int it = 0; it < KITERS; ++it) {
        int buf = it & 1;
        if (it + 1 < KITERS) {
            LOAD_TILE(it + 1, buf ^ 1);
            asm volatile("cp.async.wait_group 1;\n");
        } else {
            asm volatile("cp.async.wait_group 0;\n");
        }
        __syncthreads();

#pragma unroll
        for (int ks = 0; ks < 2; ++ks) {
            const int kk = ks * 8 + (lane & 3);
            uint32_t ah[2][4], al[2][4], bh[4][2], bl[4][2];
#pragma unroll
            for (int mf = 0; mf < 2; ++mf) {
                int r = warp_m * 32 + mf * 16 + (lane >> 2);
                split_tf32(As[buf][r][kk],          ah[mf][0], al[mf][0]);
                split_tf32(As[buf][r + 8][kk],      ah[mf][1], al[mf][1]);
                split_tf32(As[buf][r][kk + 4],      ah[mf][2], al[mf][2]);
                split_tf32(As[buf][r + 8][kk + 4],  ah[mf][3], al[mf][3]);
            }
#pragma unroll
            for (int nf = 0; nf < 4; ++nf) {
                int cn = warp_n * 32 + nf * 8 + (lane >> 2);
                split_tf32(Bs[buf][kk][cn],     bh[nf][0], bl[nf][0]);
                split_tf32(Bs[buf][kk + 4][cn], bh[nf][1], bl[nf][1]);
            }
#pragma unroll
            for (int mf = 0; mf < 2; ++mf)
#pragma unroll
                for (int nf = 0; nf < 4; ++nf) {
                    mma_tf32(acc[mf][nf], al[mf], bh[nf]);   // lo*hi
                    mma_tf32(acc[mf][nf], ah[mf], bl[nf]);   // hi*lo
                    mma_tf32(acc[mf][nf], ah[mf], bh[nf]);   // hi*hi
                }
        }
        __syncthreads();
    }

    // ---- epilogue: bias + store ----
#pragma unroll
    for (int mf = 0; mf < 2; ++mf) {
        int r = bm + warp_m * 32 + mf * 16 + (lane >> 2);
#pragma unroll
        for (int nf = 0; nf < 4; ++nf) {
            int cg = bn + warp_n * 32 + nf * 8 + 2 * (lane & 3);
            float bv0 = bias[cg], bv1 = bias[cg + 1];
            float2 v0 = make_float2(acc[mf][nf][0] + bv0, acc[mf][nf][1] + bv1);
            float2 v1 = make_float2(acc[mf][nf][2] + bv0, acc[mf][nf][3] + bv1);
            *(float2*)&Y[r * Edim + cg] = v0;
            *(float2*)&Y[(r + 8) * Edim + cg] = v1;
        }
    }
#undef LOAD_TILE
}

// ---------------------------------------------------------------------------
// Windowed attention. Block: 256 thr (8 warps), TS=32 positions per (b,h).
// ---------------------------------------------------------------------------
#define TS 32
#define ROWS (TS + 128)          // 160
#define RP 33                    // padded row stride

__global__ __launch_bounds__(256) void attn_kernel(
    const float* __restrict__ q, const float* __restrict__ k,
    const float* __restrict__ v, float* __restrict__ ctx,
    float* __restrict__ attn_out)
{
    __shared__ float ks[ROWS * RP];
    __shared__ float vs[ROWS * RP];
    __shared__ float p_sm[8][132];

    const int b    = blockIdx.z;
    const int h    = blockIdx.y;
    const int s0   = blockIdx.x * TS;
    const int t    = threadIdx.x;
    const int lane = t & 31;
    const int warp = t >> 5;

    const int base = (b * Sdim) * Edim + h * HD;

#pragma unroll
    for (int it = 0; it < ROWS / 8; ++it) {
        int r = warp + it * 8;
        int tok = s0 - OFF + r;
        tok = min(max(tok, 0), Sdim - 1);
        int g = base + tok * Edim + lane;
        ks[r * RP + lane] = k[g];
        vs[r * RP + lane] = v[g];
    }
    __syncthreads();

    const float scale = 0.17677669529663689f;  // 1/sqrt(32)

    for (int i = 0; i < TS / 8; ++i) {
        int sl = warp * (TS / 8) + i;
        int s  = s0 + sl;
        float qd = q[base + s * Edim + lane];

        int r0 = (sl + lane +  0) * RP;
        int r1 = (sl + lane + 32) * RP;
        int r2 = (sl + lane + 64) * RP;
        int r3 = (sl + lane + 96) * RP;
        int r4 = min(sl + lane + 128, ROWS - 1) * RP;

        float sum0 = 0.f, sum1 = 0.f, sum2 = 0.f, sum3 = 0.f, sum4 = 0.f;
#pragma unroll
        for (int d = 0; d < HD; ++d) {
            float a = __shfl_sync(FULL, qd, d);
            sum0 = fmaf(a, ks[r0 + d], sum0);
            sum1 = fmaf(a, ks[r1 + d], sum1);
            sum2 = fmaf(a, ks[r2 + d], sum2);
            sum3 = fmaf(a, ks[r3 + d], sum3);
            sum4 = fmaf(a, ks[r4 + d], sum4);
        }

        float sc[5];
        {
            int w, idx;
            w = lane +  0; idx = s + w - OFF;
            sc[0] = (idx >= 0 && idx < Sdim) ? sum0 * scale : -1e9f;
            w = lane + 32; idx = s + w - OFF;
            sc[1] = (idx >= 0 && idx < Sdim) ? sum1 * scale : -1e9f;
            w = lane + 64; idx = s + w - OFF;
            sc[2] = (idx >= 0 && idx < Sdim) ? sum2 * scale : -1e9f;
            w = lane + 96; idx = s + w - OFF;
            sc[3] = (idx >= 0 && idx < Sdim) ? sum3 * scale : -1e9f;
            idx = s + 128 - OFF;
            sc[4] = (lane == 0) ? ((idx < Sdim) ? sum4 * scale : -1e9f)
                                : -INFINITY;
        }

        float m = sc[0];
#pragma unroll
        for (int j = 1; j < 5; ++j) m = fmaxf(m, sc[j]);
#pragma unroll
        for (int o = 16; o; o >>= 1) m = fmaxf(m, __shfl_xor_sync(FULL, m, o));

        float ex[5], lsum = 0.f;
#pragma unroll
        for (int j = 0; j < 5; ++j) { ex[j] = expf(sc[j] - m); lsum += ex[j]; }
#pragma unroll
        for (int o = 16; o; o >>= 1) lsum += __shfl_xor_sync(FULL, lsum, o);
        float inv = 1.f / lsum;

        int arow = ((b * Hn + h) * Sdim + s) * WIN;
#pragma unroll
        for (int j = 0; j < 4; ++j) {
            int w = lane + 32 * j;
            float p = ex[j] * inv;
            p_sm[warp][w] = p;
            if (attn_out) attn_out[arow + w] = p;
        }
        if (lane == 0) {
            float p = ex[4] * inv;
            p_sm[warp][128] = p;
            if (attn_out) attn_out[arow + 128] = p;
        }
        __syncwarp();

        float cacc = 0.f;
        int vb = sl * RP + lane;
#pragma unroll 8
        for (int w = 0; w < WIN; ++w)
            cacc = fmaf(p_sm[warp][w], vs[vb + w * RP], cacc);

        ctx[base + s * Edim + lane] = cacc;
        __syncwarp();
    }
}

// ---------------------------------------------------------------------------
extern "C" void kernel_launch(void* const* d_in, const int* in_sizes, int n_in,
                              void* d_out, int out_size) {
    const float* x  = (const float*)d_in[0];
    const float* Wq = (const float*)d_in[1];
    const float* bq = (const float*)d_in[2];
    const float* Wk = (const float*)d_in[3];
    const float* bk = (const float*)d_in[4];
    const float* Wv = (const float*)d_in[5];
    const float* bv = (const float*)d_in[6];
    const float* Wo = (const float*)d_in[7];
    const float* bo = (const float*)d_in[8];
    float* out = (float*)d_out;

    float *xpe, *q, *k, *v, *ctx;
    cudaGetSymbolAddress((void**)&xpe, g_xpe);
    cudaGetSymbolAddress((void**)&q,   g_q);
    cudaGetSymbolAddress((void**)&k,   g_k);
    cudaGetSymbolAddress((void**)&v,   g_v);
    cudaGetSymbolAddress((void**)&ctx, g_ctx);

    const long OUT_ELEMS  = (long)Bz * Sdim * Edim;                 // 1,048,576
    const long ATTN_ELEMS = (long)Bz * Hn * Sdim * WIN;             // 4,227,072
    float* attn_out = nullptr;
    if ((long)out_size >= OUT_ELEMS + ATTN_ELEMS) attn_out = out + OUT_ELEMS;

    add_pe_kernel<<<MTOK * Edim / 256, 256>>>(x, xpe);

    // Fused Q/K/V projections: grid.y 0-3 -> Wq, 4-7 -> Wk, 8-11 -> Wv
    gemm_tc_kernel<<<dim3(MTOK / GBM, 12), 256>>>(
        xpe, Wq, bq, q, Wk, bk, k, Wv, bv, v);

    attn_kernel<<<dim3(Sdim / TS, Hn, Bz), 256>>>(q, k, v, ctx, attn_out);

    // Output projection: grid.y 0-3 -> Wo only
    gemm_tc_kernel<<<dim3(MTOK / GBM, 4), 256>>>(
        ctx, Wo, bo, out, Wo, bo, out, Wo, bo, out);
}

// round 6
// speedup vs baseline: 1.3448x; 1.0086x over previous
#include <cuda_runtime.h>
#include <math.h>
#include <stdint.h>

#define FULL 0xffffffffu

// Problem constants
#define Bz 2
#define Sdim 2048
#define Edim 256
#define Hn 8
#define HD 32
#define WIN 129
#define OFF 64
#define MTOK (Bz*Sdim)          // 4096 token rows

// Scratch (no cudaMalloc allowed)
__device__ float g_xpe[MTOK*Edim];
__device__ float g_q[MTOK*Edim];
__device__ float g_k[MTOK*Edim];
__device__ float g_v[MTOK*Edim];
__device__ float g_ctx[MTOK*Edim];

// ---------------------------------------------------------------------------
// x + sinusoidal positional encoding
// ---------------------------------------------------------------------------
__global__ void add_pe_kernel(const float* __restrict__ x, float* __restrict__ y) {
    int i = blockIdx.x * 256 + threadIdx.x;
    int e = i & (Edim - 1);
    int s = (i >> 8) & (Sdim - 1);
    float dv = expf((float)(e >> 1) * (-2.0f * 9.210340371976184f / 256.0f));
    float ang = (float)s * dv;
    float pe = (e & 1) ? cosf(ang) : sinf(ang);
    y[i] = x[i] + pe;
}

// ---------------------------------------------------------------------------
// 3xTF32 tensor-core GEMM: Y[M,256] = X[M,256] @ W[256,256] + bias
// CTA tile 64x64, 128 threads (4 warps, each 32x32 via 2x4 m16n8k8 frags).
// K chunk 32, double-buffered cp.async. QKV fused via grid.y.
// ---------------------------------------------------------------------------
#define GBM 64
#define GBN 64
#define GBK 32
#define APAD 36   // row stride (floats); 36 = 4*9, float4-aligned, conflict-free frags
#define BPAD 72

__device__ __forceinline__ void cp16(void* smem, const void* g) {
    uint32_t s = (uint32_t)__cvta_generic_to_shared(smem);
    asm volatile("cp.async.cg.shared.global [%0], [%1], 16;\n" :: "r"(s), "l"(g));
}
__device__ __forceinline__ void cp_commit() {
    asm volatile("cp.async.commit_group;\n");
}
__device__ __forceinline__ void split_tf32(float x, uint32_t& hi, uint32_t& lo) {
    asm("cvt.rna.tf32.f32 %0, %1;" : "=r"(hi) : "f"(x));
    float l = x - __uint_as_float(hi);
    asm("cvt.rna.tf32.f32 %0, %1;" : "=r"(lo) : "f"(l));
}
__device__ __forceinline__ void mma_tf32(float* acc, const uint32_t* a, const uint32_t* b) {
    asm volatile(
        "mma.sync.aligned.m16n8k8.row.col.f32.tf32.tf32.f32 "
        "{%0,%1,%2,%3}, {%4,%5,%6,%7}, {%8,%9}, {%0,%1,%2,%3};\n"
        : "+f"(acc[0]), "+f"(acc[1]), "+f"(acc[2]), "+f"(acc[3])
        : "r"(a[0]), "r"(a[1]), "r"(a[2]), "r"(a[3]), "r"(b[0]), "r"(b[1]));
}

__global__ __launch_bounds__(128) void gemm_tc_kernel(
    const float* __restrict__ X,
    const float* __restrict__ W0, const float* __restrict__ b0, float* __restrict__ Y0,
    const float* __restrict__ W1, const float* __restrict__ b1, float* __restrict__ Y1,
    const float* __restrict__ W2, const float* __restrict__ b2, float* __restrict__ Y2)
{
    __shared__ float As[2][GBM][APAD];
    __shared__ float Bs[2][GBK][BPAD];

    const int t    = threadIdx.x;
    const int lane = t & 31;
    const int warp = t >> 5;
    const int warp_m = warp & 1;     // 2 m-tiles of 32
    const int warp_n = warp >> 1;    // 2 n-tiles of 32

    const int bm = blockIdx.x * GBM;
    const int wsel = blockIdx.y >> 2;
    const int bn = (blockIdx.y & 3) * GBN;

    const float* W    = (wsel == 0) ? W0 : ((wsel == 1) ? W1 : W2);
    const float* bias = (wsel == 0) ? b0 : ((wsel == 1) ? b1 : b2);
    float*       Y    = (wsel == 0) ? Y0 : ((wsel == 1) ? Y1 : Y2);

    float acc[2][4][4];
#pragma unroll
    for (int mf = 0; mf < 2; ++mf)
#pragma unroll
        for (int nf = 0; nf < 4; ++nf)
#pragma unroll
            for (int r = 0; r < 4; ++r) acc[mf][nf][r] = 0.f;

    // Tile loader (128 thr): A 64x32 = 512 float4 (4/thr), B 32x64 = 512 float4 (4/thr)
#define LOAD_TILE(it, buf)                                                       \
    do {                                                                         \
        int k0_ = (it) * GBK;                                                    \
        _Pragma("unroll")                                                        \
        for (int c = 0; c < 4; ++c) {                                            \
            int f = t + c * 128;                                                 \
            int m_ = f >> 3, kq_ = (f & 7) << 2;                                 \
            cp16(&As[buf][m_][kq_], &X[(bm + m_) * Edim + k0_ + kq_]);           \
        }                                                                        \
        _Pragma("unroll")                                                        \
        for (int c = 0; c < 4; ++c) {                                            \
            int f = t + c * 128;                                                 \
            int kk_ = f >> 4, nq_ = (f & 15) << 2;                               \
            cp16(&Bs[buf][kk_][nq_], &W[(k0_ + kk_) * Edim + bn + nq_]);         \
        }                                                                        \
        cp_commit();                                                             \
    } while (0)

    LOAD_TILE(0, 0);

    const int KITERS = Edim / GBK;   // 8
    for (int it = 0; it < KITERS; ++it) {
        int buf = it & 1;
        if (it + 1 < KITERS) {
            LOAD_TILE(it + 1, buf ^ 1);
            asm volatile("cp.async.wait_group 1;\n");
        } else {
            asm volatile("cp.async.wait_group 0;\n");
        }
        __syncthreads();

#pragma unroll
        for (int ks = 0; ks < 4; ++ks) {
            const int kk = ks * 8 + (lane & 3);
            uint32_t ah[2][4], al[2][4], bh[4][2], bl[4][2];
#pragma unroll
            for (int mf = 0; mf < 2; ++mf) {
                int r = warp_m * 32 + mf * 16 + (lane >> 2);
                split_tf32(As[buf][r][kk],          ah[mf][0], al[mf][0]);
                split_tf32(As[buf][r + 8][kk],      ah[mf][1], al[mf][1]);
                split_tf32(As[buf][r][kk + 4],      ah[mf][2], al[mf][2]);
                split_tf32(As[buf][r + 8][kk + 4],  ah[mf][3], al[mf][3]);
            }
#pragma unroll
            for (int nf = 0; nf < 4; ++nf) {
                int cn = warp_n * 32 + nf * 8 + (lane >> 2);
                split_tf32(Bs[buf][kk][cn],     bh[nf][0], bl[nf][0]);
                split_tf32(Bs[buf][kk + 4][cn], bh[nf][1], bl[nf][1]);
            }
#pragma unroll
            for (int mf = 0; mf < 2; ++mf)
#pragma unroll
                for (int nf = 0; nf < 4; ++nf) {
                    mma_tf32(acc[mf][nf], al[mf], bh[nf]);   // lo*hi
                    mma_tf32(acc[mf][nf], ah[mf], bl[nf]);   // hi*lo
                    mma_tf32(acc[mf][nf], ah[mf], bh[nf]);   // hi*hi
                }
        }
        __syncthreads();
    }

    // ---- epilogue: bias + store ----
#pragma unroll
    for (int mf = 0; mf < 2; ++mf) {
        int r = bm + warp_m * 32 + mf * 16 + (lane >> 2);
#pragma unroll
        for (int nf = 0; nf < 4; ++nf) {
            int cg = bn + warp_n * 32 + nf * 8 + 2 * (lane & 3);
            float bv0 = bias[cg], bv1 = bias[cg + 1];
            float2 v0 = make_float2(acc[mf][nf][0] + bv0, acc[mf][nf][1] + bv1);
            float2 v1 = make_float2(acc[mf][nf][2] + bv0, acc[mf][nf][3] + bv1);
            *(float2*)&Y[r * Edim + cg] = v0;
            *(float2*)&Y[(r + 8) * Edim + cg] = v1;
        }
    }
#undef LOAD_TILE
}

// ---------------------------------------------------------------------------
// Windowed attention. Block: 256 thr (8 warps), TS=32 positions per (b,h).
// ---------------------------------------------------------------------------
#define TS 32
#define ROWS (TS + 128)          // 160
#define RP 33                    // padded row stride

__global__ __launch_bounds__(256) void attn_kernel(
    const float* __restrict__ q, const float* __restrict__ k,
    const float* __restrict__ v, float* __restrict__ ctx,
    float* __restrict__ attn_out)
{
    __shared__ float ks[ROWS * RP];
    __shared__ float vs[ROWS * RP];
    __shared__ float p_sm[8][132];

    const int b    = blockIdx.z;
    const int h    = blockIdx.y;
    const int s0   = blockIdx.x * TS;
    const int t    = threadIdx.x;
    const int lane = t & 31;
    const int warp = t >> 5;

    const int base = (b * Sdim) * Edim + h * HD;

#pragma unroll
    for (int it = 0; it < ROWS / 8; ++it) {
        int r = warp + it * 8;
        int tok = s0 - OFF + r;
        tok = min(max(tok, 0), Sdim - 1);
        int g = base + tok * Edim + lane;
        ks[r * RP + lane] = k[g];
        vs[r * RP + lane] = v[g];
    }
    __syncthreads();

    const float scale = 0.17677669529663689f;  // 1/sqrt(32)

    for (int i = 0; i < TS / 8; ++i) {
        int sl = warp * (TS / 8) + i;
        int s  = s0 + sl;
        float qd = q[base + s * Edim + lane];

        int r0 = (sl + lane +  0) * RP;
        int r1 = (sl + lane + 32) * RP;
        int r2 = (sl + lane + 64) * RP;
        int r3 = (sl + lane + 96) * RP;
        int r4 = min(sl + lane + 128, ROWS - 1) * RP;

        float sum0 = 0.f, sum1 = 0.f, sum2 = 0.f, sum3 = 0.f, sum4 = 0.f;
#pragma unroll
        for (int d = 0; d < HD; ++d) {
            float a = __shfl_sync(FULL, qd, d);
            sum0 = fmaf(a, ks[r0 + d], sum0);
            sum1 = fmaf(a, ks[r1 + d], sum1);
            sum2 = fmaf(a, ks[r2 + d], sum2);
            sum3 = fmaf(a, ks[r3 + d], sum3);
            sum4 = fmaf(a, ks[r4 + d], sum4);
        }

        float sc[5];
        {
            int w, idx;
            w = lane +  0; idx = s + w - OFF;
            sc[0] = (idx >= 0 && idx < Sdim) ? sum0 * scale : -1e9f;
            w = lane + 32; idx = s + w - OFF;
            sc[1] = (idx >= 0 && idx < Sdim) ? sum1 * scale : -1e9f;
            w = lane + 64; idx = s + w - OFF;
            sc[2] = (idx >= 0 && idx < Sdim) ? sum2 * scale : -1e9f;
            w = lane + 96; idx = s + w - OFF;
            sc[3] = (idx >= 0 && idx < Sdim) ? sum3 * scale : -1e9f;
            idx = s + 128 - OFF;
            sc[4] = (lane == 0) ? ((idx < Sdim) ? sum4 * scale : -1e9f)
                                : -INFINITY;
        }

        float m = sc[0];
#pragma unroll
        for (int j = 1; j < 5; ++j) m = fmaxf(m, sc[j]);
#pragma unroll
        for (int o = 16; o; o >>= 1) m = fmaxf(m, __shfl_xor_sync(FULL, m, o));

        float ex[5], lsum = 0.f;
#pragma unroll
        for (int j = 0; j < 5; ++j) { ex[j] = expf(sc[j] - m); lsum += ex[j]; }
#pragma unroll
        for (int o = 16; o; o >>= 1) lsum += __shfl_xor_sync(FULL, lsum, o);
        float inv = 1.f / lsum;

        int arow = ((b * Hn + h) * Sdim + s) * WIN;
#pragma unroll
        for (int j = 0; j < 4; ++j) {
            int w = lane + 32 * j;
            float p = ex[j] * inv;
            p_sm[warp][w] = p;
            if (attn_out) attn_out[arow + w] = p;
        }
        if (lane == 0) {
            float p = ex[4] * inv;
            p_sm[warp][128] = p;
            if (attn_out) attn_out[arow + 128] = p;
        }
        __syncwarp();

        float cacc = 0.f;
        int vb = sl * RP + lane;
#pragma unroll 8
        for (int w = 0; w < WIN; ++w)
            cacc = fmaf(p_sm[warp][w], vs[vb + w * RP], cacc);

        ctx[base + s * Edim + lane] = cacc;
        __syncwarp();
    }
}

// ---------------------------------------------------------------------------
extern "C" void kernel_launch(void* const* d_in, const int* in_sizes, int n_in,
                              void* d_out, int out_size) {
    const float* x  = (const float*)d_in[0];
    const float* Wq = (const float*)d_in[1];
    const float* bq = (const float*)d_in[2];
    const float* Wk = (const float*)d_in[3];
    const float* bk = (const float*)d_in[4];
    const float* Wv = (const float*)d_in[5];
    const float* bv = (const float*)d_in[6];
    const float* Wo = (const float*)d_in[7];
    const float* bo = (const float*)d_in[8];
    float* out = (float*)d_out;

    float *xpe, *q, *k, *v, *ctx;
    cudaGetSymbolAddress((void**)&xpe, g_xpe);
    cudaGetSymbolAddress((void**)&q,   g_q);
    cudaGetSymbolAddress((void**)&k,   g_k);
    cudaGetSymbolAddress((void**)&v,   g_v);
    cudaGetSymbolAddress((void**)&ctx, g_ctx);

    const long OUT_ELEMS  = (long)Bz * Sdim * Edim;                 // 1,048,576
    const long ATTN_ELEMS = (long)Bz * Hn * Sdim * WIN;             // 4,227,072
    float* attn_out = nullptr;
    if ((long)out_size >= OUT_ELEMS + ATTN_ELEMS) attn_out = out + OUT_ELEMS;

    add_pe_kernel<<<MTOK * Edim / 256, 256>>>(x, xpe);

    // Fused Q/K/V projections: grid.y 0-3 -> Wq, 4-7 -> Wk, 8-11 -> Wv
    gemm_tc_kernel<<<dim3(MTOK / GBM, 12), 128>>>(
        xpe, Wq, bq, q, Wk, bk, k, Wv, bv, v);

    attn_kernel<<<dim3(Sdim / TS, Hn, Bz), 256>>>(q, k, v, ctx, attn_out);

    // Output projection: grid.y 0-3 -> Wo only
    gemm_tc_kernel<<<dim3(MTOK / GBM, 4), 128>>>(
        ctx, Wo, bo, out, Wo, bo, out, Wo, bo, out);
}